// round 4
// baseline (speedup 1.0000x reference)
#include <cuda_runtime.h>

#define NN 50000
#define DD 128
#define EE 600000
#define GG 512
#define LLAYERS 3
#define EDIM 16
#define JKD 384
#define TILE_R 96
#define NODE_T 192
#define NTILES ((NN + TILE_R - 1) / TILE_R)
#define SCAN_BS 256
#define SCAN_NBLK ((NN + SCAN_BS - 1) / SCAN_BS)

typedef unsigned long long u64;

// Scratch (device globals: no runtime allocation allowed)
__device__ float g_xcur[NN * DD];          // 25.6 MB
__device__ float g_agg[NN * DD];           // 25.6 MB
__device__ float g_pool[GG * JKD];         // 0.79 MB
__device__ int   g_cnt[NN];
__device__ int   g_scan[NN];
__device__ int   g_off[NN + 1];
__device__ int   g_cursor[NN];
__device__ int   g_blocksum[SCAN_BS];
__device__ int   g_bloff[SCAN_BS];
__device__ int   g_csr_src[EE];
__device__ int   g_csr_eid[EE];

// ---------------------------------------------------------------------------
// packed f32x2 helpers (sm_103a)
// ---------------------------------------------------------------------------
__device__ __forceinline__ u64 pack2(float x, float y) {
    u64 r; asm("mov.b64 %0, {%1, %2};" : "=l"(r) : "f"(x), "f"(y)); return r;
}
__device__ __forceinline__ float2 unpack2(u64 v) {
    float2 r; asm("mov.b64 {%0, %1}, %2;" : "=f"(r.x), "=f"(r.y) : "l"(v)); return r;
}
__device__ __forceinline__ void fma2(u64& d, u64 a, u64 b) {
    asm("fma.rn.f32x2 %0, %1, %2, %0;" : "+l"(d) : "l"(a), "l"(b));
}
__device__ __forceinline__ u64 add2(u64 a, u64 b) {
    u64 r; asm("add.rn.f32x2 %0, %1, %2;" : "=l"(r) : "l"(a), "l"(b)); return r;
}

// ---------------------------------------------------------------------------
// init: x_cur = x + vn_emb[0]
// ---------------------------------------------------------------------------
__global__ void init_kernel(const float* __restrict__ x, const float* __restrict__ vn0) {
    int i = blockIdx.x * blockDim.x + threadIdx.x;   // float4 index
    if (i >= NN * DD / 4) return;
    float4 xv = reinterpret_cast<const float4*>(x)[i];
    float4 vv = reinterpret_cast<const float4*>(vn0)[i & 31];
    xv.x += vv.x; xv.y += vv.y; xv.z += vv.z; xv.w += vv.w;
    reinterpret_cast<float4*>(g_xcur)[i] = xv;
    reinterpret_cast<float4*>(g_agg)[i] = make_float4(0.f, 0.f, 0.f, 0.f);
}

// ---------------------------------------------------------------------------
// CSR build (once per launch): histogram -> scan -> scatter by dst
// NOTE: grid for k_zero must cover BOTH NN counters and GG*JKD/4 pool vecs —
// R3 failed because g_cnt[49152..49999] were never re-zeroed across replays.
// ---------------------------------------------------------------------------
#define ZERO_N ((NN > GG * JKD / 4) ? NN : (GG * JKD / 4))

__global__ void k_zero_cnt() {
    int i = blockIdx.x * blockDim.x + threadIdx.x;
    if (i < NN) g_cnt[i] = 0;
    if (i < GG * JKD / 4)
        reinterpret_cast<float4*>(g_pool)[i] = make_float4(0.f, 0.f, 0.f, 0.f);
}

__global__ void k_hist(const int* __restrict__ ei) {
    int e = blockIdx.x * blockDim.x + threadIdx.x;
    if (e < EE) atomicAdd(&g_cnt[ei[EE + e]], 1);
}

__global__ __launch_bounds__(SCAN_BS) void k_scan1() {
    __shared__ int s[SCAN_BS];
    const int t = threadIdx.x;
    const int i = blockIdx.x * SCAN_BS + t;
    int v = (i < NN) ? g_cnt[i] : 0;
    s[t] = v;
    __syncthreads();
#pragma unroll
    for (int o = 1; o < SCAN_BS; o <<= 1) {
        int u = (t >= o) ? s[t - o] : 0;
        __syncthreads();
        s[t] += u;
        __syncthreads();
    }
    if (i < NN) g_scan[i] = s[t];
    if (t == SCAN_BS - 1) g_blocksum[blockIdx.x] = s[t];
}

__global__ __launch_bounds__(SCAN_BS) void k_scan2() {
    __shared__ int s[SCAN_BS];
    const int t = threadIdx.x;
    int v = (t < SCAN_NBLK) ? g_blocksum[t] : 0;
    s[t] = v;
    __syncthreads();
#pragma unroll
    for (int o = 1; o < SCAN_BS; o <<= 1) {
        int u = (t >= o) ? s[t - o] : 0;
        __syncthreads();
        s[t] += u;
        __syncthreads();
    }
    if (t < SCAN_NBLK) g_bloff[t] = s[t] - v;   // exclusive
}

__global__ void k_scan3() {
    int i = blockIdx.x * blockDim.x + threadIdx.x;
    if (i < NN) {
        int off = g_scan[i] - g_cnt[i] + g_bloff[i / SCAN_BS];  // exclusive
        g_off[i] = off;
        g_cursor[i] = off;
    }
    if (i == 0) g_off[NN] = EE;
}

__global__ void k_scatter(const int* __restrict__ ei) {
    int e = blockIdx.x * blockDim.x + threadIdx.x;
    if (e >= EE) return;
    int dst = ei[EE + e];
    int pos = atomicAdd(&g_cursor[dst], 1);
    g_csr_src[pos] = ei[e];
    g_csr_eid[pos] = e;
}

// ---------------------------------------------------------------------------
// Aggregation: warp per node. agg[n] = sum_{e in in(n)} relu(x[src_e] + We@a_e + be)
// Weights in registers, packed fma2 encoder, software-pipelined edge loop,
// NO atomics (register accumulation + single store).
// ---------------------------------------------------------------------------
__global__ __launch_bounds__(256, 2) void agg_kernel(
    const float* __restrict__ ea,
    const float* __restrict__ ew, const float* __restrict__ ebias)
{
    const int lane = threadIdx.x & 31;

    // per-lane weight slice: rows 0..15, cols [lane*4, lane*4+4), as 2 packed pairs
    u64 w0[EDIM], w1[EDIM];
#pragma unroll
    for (int k = 0; k < EDIM; k++) {
        const float4 wv = *reinterpret_cast<const float4*>(&ew[k * DD + lane * 4]);
        w0[k] = pack2(wv.x, wv.y);
        w1[k] = pack2(wv.z, wv.w);
    }
    const float4 bq = *reinterpret_cast<const float4*>(&ebias[lane * 4]);
    const u64 b0 = pack2(bq.x, bq.y), b1 = pack2(bq.z, bq.w);

    const int warp = (blockIdx.x * blockDim.x + threadIdx.x) >> 5;
    const int nw = (gridDim.x * blockDim.x) >> 5;

    for (int n = warp; n < NN; n += nw) {
        const int beg = g_off[n];
        const int end = g_off[n + 1];
        float4 acc = make_float4(0.f, 0.f, 0.f, 0.f);

        if (beg < end) {
            int src = g_csr_src[beg];
            int eid = g_csr_eid[beg];
            float a = (lane < EDIM) ? ea[(size_t)eid * EDIM + lane] : 0.f;
            float4 xv = *reinterpret_cast<const float4*>(&g_xcur[(size_t)src * DD + lane * 4]);

            for (int j = beg; ; ) {
                const int jn = j + 1;
                const bool more = jn < end;
                int nsrc = 0;
                float na = 0.f;
                if (more) {
                    nsrc = g_csr_src[jn];
                    const int neid = g_csr_eid[jn];
                    na = (lane < EDIM) ? ea[(size_t)neid * EDIM + lane] : 0.f;
                }

                u64 e0 = b0, e1 = b1;
#pragma unroll
                for (int k = 0; k < EDIM; k++) {
                    const float ak = __shfl_sync(0xffffffffu, a, k);
                    const u64 ak2 = pack2(ak, ak);
                    fma2(e0, ak2, w0[k]);
                    fma2(e1, ak2, w1[k]);
                }

                float4 nxv = make_float4(0.f, 0.f, 0.f, 0.f);
                if (more)
                    nxv = *reinterpret_cast<const float4*>(&g_xcur[(size_t)nsrc * DD + lane * 4]);

                const float2 lo = unpack2(e0), hi = unpack2(e1);
                acc.x += fmaxf(lo.x + xv.x, 0.f);
                acc.y += fmaxf(lo.y + xv.y, 0.f);
                acc.z += fmaxf(hi.x + xv.z, 0.f);
                acc.w += fmaxf(hi.y + xv.w, 0.f);

                if (!more) break;
                j = jn; a = na; xv = nxv;
            }
        }
        *reinterpret_cast<float4*>(&g_agg[(size_t)n * DD + lane * 4]) = acc;
    }
}

// ---------------------------------------------------------------------------
// Node MLP: h=(1+eps)*x+agg; y=relu(h@W1+b1); x2=y@W2+b2
// 8x8 per-thread tile (LDS:FMA balanced), packed f32x2 FMAs.
// Fused epilogue: pool[batch[row]] += x2 (run-length reduced RED.v4);
//                 x_cur = x2 + vn[l+1] (except last layer).
// ---------------------------------------------------------------------------
__device__ __forceinline__ void tile_gemm8(
    const float* sA, const float* sW, int cg, int rg, u64 acc[8][4])
{
#pragma unroll 1
    for (int k = 0; k < DD; k += 4) {
        u64 w[4][4];
#pragma unroll
        for (int kk = 0; kk < 4; kk++) {
            const float4 wa = *reinterpret_cast<const float4*>(&sW[(k + kk) * DD + cg * 8]);
            const float4 wb = *reinterpret_cast<const float4*>(&sW[(k + kk) * DD + cg * 8 + 4]);
            w[kk][0] = pack2(wa.x, wa.y);
            w[kk][1] = pack2(wa.z, wa.w);
            w[kk][2] = pack2(wb.x, wb.y);
            w[kk][3] = pack2(wb.z, wb.w);
        }
        float4 a[8];
#pragma unroll
        for (int r = 0; r < 8; r++)
            a[r] = *reinterpret_cast<const float4*>(&sA[(rg * 8 + r) * DD + k]);
#pragma unroll
        for (int r = 0; r < 8; r++) {
            const u64 ax = pack2(a[r].x, a[r].x);
            fma2(acc[r][0], ax, w[0][0]); fma2(acc[r][1], ax, w[0][1]);
            fma2(acc[r][2], ax, w[0][2]); fma2(acc[r][3], ax, w[0][3]);
            const u64 ay = pack2(a[r].y, a[r].y);
            fma2(acc[r][0], ay, w[1][0]); fma2(acc[r][1], ay, w[1][1]);
            fma2(acc[r][2], ay, w[1][2]); fma2(acc[r][3], ay, w[1][3]);
            const u64 az = pack2(a[r].z, a[r].z);
            fma2(acc[r][0], az, w[2][0]); fma2(acc[r][1], az, w[2][1]);
            fma2(acc[r][2], az, w[2][2]); fma2(acc[r][3], az, w[2][3]);
            const u64 aw = pack2(a[r].w, a[r].w);
            fma2(acc[r][0], aw, w[3][0]); fma2(acc[r][1], aw, w[3][1]);
            fma2(acc[r][2], aw, w[3][2]); fma2(acc[r][3], aw, w[3][3]);
        }
    }
}

__global__ __launch_bounds__(NODE_T) void node_kernel(
    const float* __restrict__ w1, const float* __restrict__ b1,
    const float* __restrict__ w2, const float* __restrict__ b2,
    const float* __restrict__ epsp, const float* __restrict__ vn_next,
    const int* __restrict__ batch, int layer)
{
    extern __shared__ float sm[];
    float* sW1 = sm;                          // 64 KB
    float* sW2 = sm + DD * DD;                // 64 KB
    float* sH  = sm + 2 * DD * DD;            // 48 KB
    float* sY  = sH + TILE_R * DD;            // 48 KB
    int*   sB  = reinterpret_cast<int*>(sY + TILE_R * DD);  // 384 B
    const int t = threadIdx.x;

    for (int i = t; i < DD * DD / 4; i += NODE_T) {
        reinterpret_cast<float4*>(sW1)[i] = reinterpret_cast<const float4*>(w1)[i];
        reinterpret_cast<float4*>(sW2)[i] = reinterpret_cast<const float4*>(w2)[i];
    }
    const float epsv = 1.0f + *epsp;
    const int cg = t & 15;   // col group: 8 cols
    const int rg = t >> 4;   // row group: 8 rows

    const float4 b1a = *reinterpret_cast<const float4*>(&b1[cg * 8]);
    const float4 b1b = *reinterpret_cast<const float4*>(&b1[cg * 8 + 4]);
    const float4 b2a = *reinterpret_cast<const float4*>(&b2[cg * 8]);
    const float4 b2b = *reinterpret_cast<const float4*>(&b2[cg * 8 + 4]);

    float4 vna = make_float4(0.f, 0.f, 0.f, 0.f), vnb = vna;
    if (vn_next) {
        vna = *reinterpret_cast<const float4*>(&vn_next[cg * 8]);
        vnb = *reinterpret_cast<const float4*>(&vn_next[cg * 8 + 4]);
    }

    for (int tile = blockIdx.x; tile < NTILES; tile += gridDim.x) {
        const int row0 = tile * TILE_R;
        __syncthreads();   // protect sH/sY/sB reuse; also fences weight load (iter 0)

        // h tile = (1+eps)*x + agg ; stage batch ids
        for (int i = t; i < TILE_R; i += NODE_T)
            sB[i] = (row0 + i < NN) ? batch[row0 + i] : -1;
        for (int i = t; i < TILE_R * DD / 4; i += NODE_T) {
            const int row = row0 + (i >> 5);
            float4 hv = make_float4(0.f, 0.f, 0.f, 0.f);
            if (row < NN) {
                const int gi = row0 * (DD / 4) + i;
                const float4 xv = reinterpret_cast<const float4*>(g_xcur)[gi];
                const float4 av = reinterpret_cast<const float4*>(g_agg)[gi];
                hv.x = fmaf(epsv, xv.x, av.x);
                hv.y = fmaf(epsv, xv.y, av.y);
                hv.z = fmaf(epsv, xv.z, av.z);
                hv.w = fmaf(epsv, xv.w, av.w);
            }
            reinterpret_cast<float4*>(sH)[i] = hv;
        }
        __syncthreads();

        u64 acc[8][4];
#pragma unroll
        for (int r = 0; r < 8; r++) {
            acc[r][0] = pack2(b1a.x, b1a.y); acc[r][1] = pack2(b1a.z, b1a.w);
            acc[r][2] = pack2(b1b.x, b1b.y); acc[r][3] = pack2(b1b.z, b1b.w);
        }
        tile_gemm8(sH, sW1, cg, rg, acc);
#pragma unroll
        for (int r = 0; r < 8; r++) {
            float* dst = &sY[(rg * 8 + r) * DD + cg * 8];
            const float2 p0 = unpack2(acc[r][0]), p1 = unpack2(acc[r][1]);
            const float2 p2 = unpack2(acc[r][2]), p3 = unpack2(acc[r][3]);
            float4 va = make_float4(fmaxf(p0.x, 0.f), fmaxf(p0.y, 0.f),
                                    fmaxf(p1.x, 0.f), fmaxf(p1.y, 0.f));
            float4 vb = make_float4(fmaxf(p2.x, 0.f), fmaxf(p2.y, 0.f),
                                    fmaxf(p3.x, 0.f), fmaxf(p3.y, 0.f));
            *reinterpret_cast<float4*>(dst) = va;
            *reinterpret_cast<float4*>(dst + 4) = vb;
        }
        __syncthreads();

#pragma unroll
        for (int r = 0; r < 8; r++) {
            acc[r][0] = pack2(b2a.x, b2a.y); acc[r][1] = pack2(b2a.z, b2a.w);
            acc[r][2] = pack2(b2b.x, b2b.y); acc[r][3] = pack2(b2b.z, b2b.w);
        }
        tile_gemm8(sY, sW2, cg, rg, acc);

        // Epilogue: pool RED (run-length reduced over sorted batch) + x_cur
        u64 ps0 = 0, ps1 = 0, ps2 = 0, ps3 = 0;
        int curb = -1;
#pragma unroll
        for (int r = 0; r < 8; r++) {
            const int lrow = rg * 8 + r;
            const int row = row0 + lrow;
            if (row >= NN) break;
            const int b = sB[lrow];
            if (b != curb) {
                if (curb >= 0) {
                    float* p = &g_pool[curb * JKD + layer * DD + cg * 8];
                    const float2 q0 = unpack2(ps0), q1 = unpack2(ps1);
                    const float2 q2 = unpack2(ps2), q3 = unpack2(ps3);
                    asm volatile("red.global.add.v4.f32 [%0], {%1,%2,%3,%4};"
                                 :: "l"(p), "f"(q0.x), "f"(q0.y), "f"(q1.x), "f"(q1.y) : "memory");
                    asm volatile("red.global.add.v4.f32 [%0], {%1,%2,%3,%4};"
                                 :: "l"(p + 4), "f"(q2.x), "f"(q2.y), "f"(q3.x), "f"(q3.y) : "memory");
                }
                curb = b; ps0 = ps1 = ps2 = ps3 = 0;
            }
            ps0 = add2(ps0, acc[r][0]); ps1 = add2(ps1, acc[r][1]);
            ps2 = add2(ps2, acc[r][2]); ps3 = add2(ps3, acc[r][3]);

            if (vn_next) {
                const float2 p0 = unpack2(acc[r][0]), p1 = unpack2(acc[r][1]);
                const float2 p2 = unpack2(acc[r][2]), p3 = unpack2(acc[r][3]);
                float* dst = &g_xcur[(size_t)row * DD + cg * 8];
                *reinterpret_cast<float4*>(dst) =
                    make_float4(p0.x + vna.x, p0.y + vna.y, p1.x + vna.z, p1.y + vna.w);
                *reinterpret_cast<float4*>(dst + 4) =
                    make_float4(p2.x + vnb.x, p2.y + vnb.y, p3.x + vnb.z, p3.y + vnb.w);
            }
        }
        if (curb >= 0) {
            float* p = &g_pool[curb * JKD + layer * DD + cg * 8];
            const float2 q0 = unpack2(ps0), q1 = unpack2(ps1);
            const float2 q2 = unpack2(ps2), q3 = unpack2(ps3);
            asm volatile("red.global.add.v4.f32 [%0], {%1,%2,%3,%4};"
                         :: "l"(p), "f"(q0.x), "f"(q0.y), "f"(q1.x), "f"(q1.y) : "memory");
            asm volatile("red.global.add.v4.f32 [%0], {%1,%2,%3,%4};"
                         :: "l"(p + 4), "f"(q2.x), "f"(q2.y), "f"(q3.x), "f"(q3.y) : "memory");
        }
    }
}

// ---------------------------------------------------------------------------
// Head: Linear(384->256) -> LN -> ReLU -> Linear(256->128) -> LN -> ReLU -> Linear(128->1)
// ---------------------------------------------------------------------------
__device__ __forceinline__ float2 block_sum2(float a, float b) {
    __shared__ float2 sred[8];
    const int lane = threadIdx.x & 31, w = threadIdx.x >> 5;
#pragma unroll
    for (int o = 16; o; o >>= 1) {
        a += __shfl_down_sync(0xffffffffu, a, o);
        b += __shfl_down_sync(0xffffffffu, b, o);
    }
    if (lane == 0) sred[w] = make_float2(a, b);
    __syncthreads();
    if (w == 0) {
        float2 s = (lane < 8) ? sred[lane] : make_float2(0.f, 0.f);
#pragma unroll
        for (int o = 4; o; o >>= 1) {
            s.x += __shfl_down_sync(0xffffffffu, s.x, o);
            s.y += __shfl_down_sync(0xffffffffu, s.y, o);
        }
        if (lane == 0) sred[0] = s;
    }
    __syncthreads();
    const float2 r = sred[0];
    __syncthreads();
    return r;
}

__global__ __launch_bounds__(256) void head_kernel(
    const float* __restrict__ w1, const float* __restrict__ b1,
    const float* __restrict__ ga1, const float* __restrict__ be1,
    const float* __restrict__ w2, const float* __restrict__ b2,
    const float* __restrict__ ga2, const float* __restrict__ be2,
    const float* __restrict__ ow, const float* __restrict__ ob,
    float* __restrict__ out)
{
    __shared__ float sg[JKD];
    __shared__ float s1[256];
    const int g = blockIdx.x, t = threadIdx.x;

    for (int i = t; i < JKD; i += 256) sg[i] = g_pool[g * JKD + i];
    __syncthreads();

    // stage 1: 384 -> 256
    float acc = b1[t];
#pragma unroll 4
    for (int k = 0; k < JKD; k++) acc = fmaf(sg[k], w1[k * 256 + t], acc);
    float2 s = block_sum2(acc, acc * acc);
    float mu = s.x * (1.f / 256.f);
    float var = s.y * (1.f / 256.f) - mu * mu;
    s1[t] = fmaxf((acc - mu) * rsqrtf(var + 1e-5f) * ga1[t] + be1[t], 0.f);
    __syncthreads();

    // stage 2: 256 -> 128
    float acc2 = 0.f;
    if (t < 128) {
        acc2 = b2[t];
#pragma unroll 4
        for (int k = 0; k < 256; k++) acc2 = fmaf(s1[k], w2[k * 128 + t], acc2);
    }
    const float cva = (t < 128) ? acc2 : 0.f;
    float2 s2 = block_sum2(cva, cva * cva);
    float mu2 = s2.x * (1.f / 128.f);
    float var2 = s2.y * (1.f / 128.f) - mu2 * mu2;
    float v2 = 0.f;
    if (t < 128) v2 = fmaxf((acc2 - mu2) * rsqrtf(var2 + 1e-5f) * ga2[t] + be2[t], 0.f);

    // stage 3: 128 -> 1
    const float p = (t < 128) ? v2 * ow[t] : 0.f;
    float2 s3 = block_sum2(p, 0.f);
    if (t == 0) out[g] = s3.x + ob[0];
}

// ---------------------------------------------------------------------------
extern "C" void kernel_launch(void* const* d_in, const int* in_sizes, int n_in,
                              void* d_out, int out_size) {
    (void)in_sizes; (void)n_in; (void)out_size;
    const float* x     = (const float*)d_in[0];
    const int*   ei    = (const int*)d_in[1];
    const float* ea    = (const float*)d_in[2];
    const int*   batch = (const int*)d_in[3];
    const float* vn    = (const float*)d_in[4];
    const float* ew    = (const float*)d_in[5];
    const float* ebias = (const float*)d_in[6];
    const float* eps   = (const float*)d_in[7];
    const float* mw1   = (const float*)d_in[8];
    const float* mb1   = (const float*)d_in[9];
    const float* mw2   = (const float*)d_in[10];
    const float* mb2   = (const float*)d_in[11];
    const float* lw1   = (const float*)d_in[12];
    const float* lb1   = (const float*)d_in[13];
    const float* ln1g  = (const float*)d_in[14];
    const float* ln1b  = (const float*)d_in[15];
    const float* lw2   = (const float*)d_in[16];
    const float* lb2   = (const float*)d_in[17];
    const float* ln2g  = (const float*)d_in[18];
    const float* ln2b  = (const float*)d_in[19];
    const float* ow    = (const float*)d_in[20];
    const float* ob    = (const float*)d_in[21];
    float* out = (float*)d_out;

    int nsm = 148;
    cudaDeviceGetAttribute(&nsm, cudaDevAttrMultiProcessorCount, 0);

    const int node_smem = (2 * DD * DD + 2 * TILE_R * DD) * (int)sizeof(float)
                        + TILE_R * (int)sizeof(int);                    // ~224.4 KB
    cudaFuncSetAttribute(node_kernel, cudaFuncAttributeMaxDynamicSharedMemorySize, node_smem);

    // init + CSR build (independent of layers)
    init_kernel<<<(NN * DD / 4 + 255) / 256, 256>>>(x, vn);
    k_zero_cnt<<<(ZERO_N + 255) / 256, 256>>>();   // FIX: grid covers max(NN, pool)
    k_hist<<<(EE + 255) / 256, 256>>>(ei);
    k_scan1<<<SCAN_NBLK, SCAN_BS>>>();
    k_scan2<<<1, SCAN_BS>>>();
    k_scan3<<<(NN + 255) / 256, 256>>>();
    k_scatter<<<(EE + 255) / 256, 256>>>(ei);

    for (int i = 0; i < LLAYERS; i++) {
        agg_kernel<<<nsm * 2, 256>>>(ea, ew + i * EDIM * DD, ebias + i * DD);
        node_kernel<<<nsm, NODE_T, node_smem>>>(
            mw1 + i * DD * DD, mb1 + i * DD,
            mw2 + i * DD * DD, mb2 + i * DD,
            eps + i,
            (i < LLAYERS - 1) ? (vn + (i + 1) * DD) : nullptr,
            batch, i);
    }

    head_kernel<<<GG, 256>>>(lw1, lb1, ln1g, ln1b, lw2, lb2, ln2g, ln2b, ow, ob, out);
}

// round 5
// speedup vs baseline: 1.2063x; 1.2063x over previous
#include <cuda_runtime.h>

#define NN 50000
#define DD 128
#define EE 600000
#define GG 512
#define LLAYERS 3
#define EDIM 16
#define JKD 384
#define TILE_R 96
#define NODE_T 256
#define NTILES ((NN + TILE_R - 1) / TILE_R)
#define SCAN_BS 256
#define SCAN_NBLK ((NN + SCAN_BS - 1) / SCAN_BS)

typedef unsigned long long u64;

// Scratch (device globals: no runtime allocation allowed)
__device__ float g_xcur[NN * DD];          // 25.6 MB
__device__ float g_agg[NN * DD];           // 25.6 MB
__device__ float g_pool[GG * JKD];         // 0.79 MB
__device__ int   g_cnt[NN];
__device__ int   g_scan[NN];
__device__ int   g_cursor[NN];
__device__ int   g_blocksum[SCAN_BS];
__device__ int   g_bloff[SCAN_BS];
__device__ int   g_csr_src[EE];
__device__ int   g_csr_dst[EE];
__device__ float g_csr_ea[(size_t)EE * EDIM];   // 38.4 MB, edge attrs in CSR order

// ---------------------------------------------------------------------------
// packed f32x2 helpers (sm_103a)
// ---------------------------------------------------------------------------
__device__ __forceinline__ u64 pack2(float x, float y) {
    u64 r; asm("mov.b64 %0, {%1, %2};" : "=l"(r) : "f"(x), "f"(y)); return r;
}
__device__ __forceinline__ float2 unpack2(u64 v) {
    float2 r; asm("mov.b64 {%0, %1}, %2;" : "=f"(r.x), "=f"(r.y) : "l"(v)); return r;
}
__device__ __forceinline__ void fma2(u64& d, u64 a, u64 b) {
    asm("fma.rn.f32x2 %0, %1, %2, %0;" : "+l"(d) : "l"(a), "l"(b));
}
__device__ __forceinline__ u64 add2(u64 a, u64 b) {
    u64 r; asm("add.rn.f32x2 %0, %1, %2;" : "=l"(r) : "l"(a), "l"(b)); return r;
}
__device__ __forceinline__ void red_v4(float* p, float4 v) {
    asm volatile("red.global.add.v4.f32 [%0], {%1,%2,%3,%4};"
                 :: "l"(p), "f"(v.x), "f"(v.y), "f"(v.z), "f"(v.w) : "memory");
}

// ---------------------------------------------------------------------------
// init: x_cur = x + vn_emb[0]; agg = 0 (layer-0 base for RED / degree-0 nodes)
// ---------------------------------------------------------------------------
__global__ void init_kernel(const float* __restrict__ x, const float* __restrict__ vn0) {
    int i = blockIdx.x * blockDim.x + threadIdx.x;   // float4 index
    if (i >= NN * DD / 4) return;
    float4 xv = reinterpret_cast<const float4*>(x)[i];
    float4 vv = reinterpret_cast<const float4*>(vn0)[i & 31];
    xv.x += vv.x; xv.y += vv.y; xv.z += vv.z; xv.w += vv.w;
    reinterpret_cast<float4*>(g_xcur)[i] = xv;
    reinterpret_cast<float4*>(g_agg)[i] = make_float4(0.f, 0.f, 0.f, 0.f);
}

// ---------------------------------------------------------------------------
// CSR build: histogram -> scan -> scatter (records: src, dst, attr copy)
// ---------------------------------------------------------------------------
#define ZERO_N ((NN > GG * JKD / 4) ? NN : (GG * JKD / 4))

__global__ void k_zero_cnt() {
    int i = blockIdx.x * blockDim.x + threadIdx.x;
    if (i < NN) g_cnt[i] = 0;
    if (i < GG * JKD / 4)
        reinterpret_cast<float4*>(g_pool)[i] = make_float4(0.f, 0.f, 0.f, 0.f);
}

__global__ void k_hist(const int* __restrict__ ei) {
    int e = blockIdx.x * blockDim.x + threadIdx.x;
    if (e < EE) atomicAdd(&g_cnt[ei[EE + e]], 1);
}

__global__ __launch_bounds__(SCAN_BS) void k_scan1() {
    __shared__ int s[SCAN_BS];
    const int t = threadIdx.x;
    const int i = blockIdx.x * SCAN_BS + t;
    int v = (i < NN) ? g_cnt[i] : 0;
    s[t] = v;
    __syncthreads();
#pragma unroll
    for (int o = 1; o < SCAN_BS; o <<= 1) {
        int u = (t >= o) ? s[t - o] : 0;
        __syncthreads();
        s[t] += u;
        __syncthreads();
    }
    if (i < NN) g_scan[i] = s[t];
    if (t == SCAN_BS - 1) g_blocksum[blockIdx.x] = s[t];
}

__global__ __launch_bounds__(SCAN_BS) void k_scan2() {
    __shared__ int s[SCAN_BS];
    const int t = threadIdx.x;
    int v = (t < SCAN_NBLK) ? g_blocksum[t] : 0;
    s[t] = v;
    __syncthreads();
#pragma unroll
    for (int o = 1; o < SCAN_BS; o <<= 1) {
        int u = (t >= o) ? s[t - o] : 0;
        __syncthreads();
        s[t] += u;
        __syncthreads();
    }
    if (t < SCAN_NBLK) g_bloff[t] = s[t] - v;   // exclusive
}

__global__ void k_scan3() {
    int i = blockIdx.x * blockDim.x + threadIdx.x;
    if (i < NN)
        g_cursor[i] = g_scan[i] - g_cnt[i] + g_bloff[i / SCAN_BS];  // exclusive
}

__global__ void k_scatter(const int* __restrict__ ei, const float* __restrict__ ea) {
    int e = blockIdx.x * blockDim.x + threadIdx.x;
    if (e >= EE) return;
    const int dst = ei[EE + e];
    const int pos = atomicAdd(&g_cursor[dst], 1);
    g_csr_src[pos] = ei[e];
    g_csr_dst[pos] = dst;
    const float4* q = reinterpret_cast<const float4*>(&ea[(size_t)e * EDIM]);
    float4* s = reinterpret_cast<float4*>(&g_csr_ea[(size_t)pos * EDIM]);
    s[0] = q[0]; s[1] = q[1]; s[2] = q[2]; s[3] = q[3];
}

// ---------------------------------------------------------------------------
// Aggregation: flat edge partition over the dst-sorted CSR stream.
// Each warp owns a contiguous edge range (perfect balance). Accumulates
// relu(x[src] + We@attr + be) in registers; on dst change: interior nodes get
// a plain STG (sole owner), range-boundary nodes get RED.v4 onto zeroed agg.
// All loads except x[src] are streaming/coalesced; x prefetched 1 edge ahead
// with src known 2 ahead.
// ---------------------------------------------------------------------------
__global__ __launch_bounds__(256, 2) void agg_kernel(
    const float* __restrict__ ew, const float* __restrict__ ebias)
{
    const int lane = threadIdx.x & 31;

    // per-lane weight slice: rows 0..15, cols [lane*4, lane*4+4), as 2 packed pairs
    u64 w0[EDIM], w1[EDIM];
#pragma unroll
    for (int k = 0; k < EDIM; k++) {
        const float4 wv = *reinterpret_cast<const float4*>(&ew[k * DD + lane * 4]);
        w0[k] = pack2(wv.x, wv.y);
        w1[k] = pack2(wv.z, wv.w);
    }
    const float4 bq = *reinterpret_cast<const float4*>(&ebias[lane * 4]);
    const u64 b0 = pack2(bq.x, bq.y), b1 = pack2(bq.z, bq.w);

    const int warp = (blockIdx.x * blockDim.x + threadIdx.x) >> 5;
    const int nw = (gridDim.x * blockDim.x) >> 5;
    const int epw = (EE + nw - 1) / nw;
    const int beg = warp * epw;
    if (beg >= EE) return;
    const int end = (beg + epw < EE) ? beg + epw : EE;

    // pipeline: edge j fully resident (a0, x0, dst0); edge j+1 (src1,dst1,a1)
    int src1 = 0, dst1 = 0;
    float a1 = 0.f;
    int dst0 = g_csr_dst[beg];
    float a0 = (lane < EDIM) ? g_csr_ea[(size_t)beg * EDIM + lane] : 0.f;
    {
        const int src0 = g_csr_src[beg];
        float4 x0_ = *reinterpret_cast<const float4*>(&g_xcur[(size_t)src0 * DD + lane * 4]);
        if (beg + 1 < end) {
            src1 = g_csr_src[beg + 1];
            dst1 = g_csr_dst[beg + 1];
            a1 = (lane < EDIM) ? g_csr_ea[(size_t)(beg + 1) * EDIM + lane] : 0.f;
        }
        // fallthrough into loop with x0_ via variable below
        float4 x0 = x0_;

        int cur = dst0;
        float4 acc = make_float4(0.f, 0.f, 0.f, 0.f);
        bool firstflush = true;

        for (int j = beg; j < end; j++) {
            const bool m1 = (j + 1 < end);
            const bool m2 = (j + 2 < end);

            // prefetch x for edge j+1 (src1 already resident)
            float4 x1 = make_float4(0.f, 0.f, 0.f, 0.f);
            if (m1)
                x1 = *reinterpret_cast<const float4*>(&g_xcur[(size_t)src1 * DD + lane * 4]);
            // prefetch record for edge j+2
            int src2 = 0, dst2 = 0;
            float a2 = 0.f;
            if (m2) {
                src2 = g_csr_src[j + 2];
                dst2 = g_csr_dst[j + 2];
                a2 = (lane < EDIM) ? g_csr_ea[(size_t)(j + 2) * EDIM + lane] : 0.f;
            }

            // encoder for edge j
            u64 e0 = b0, e1 = b1;
#pragma unroll
            for (int k = 0; k < EDIM; k++) {
                const float ak = __shfl_sync(0xffffffffu, a0, k);
                const u64 ak2 = pack2(ak, ak);
                fma2(e0, ak2, w0[k]);
                fma2(e1, ak2, w1[k]);
            }
            const float2 lo = unpack2(e0), hi = unpack2(e1);
            float4 m;
            m.x = fmaxf(lo.x + x0.x, 0.f);
            m.y = fmaxf(lo.y + x0.y, 0.f);
            m.z = fmaxf(hi.x + x0.z, 0.f);
            m.w = fmaxf(hi.y + x0.w, 0.f);

            if (dst0 != cur) {   // warp-uniform branch (dst is lane-uniform)
                float* p = &g_agg[(size_t)cur * DD + lane * 4];
                if (firstflush) red_v4(p, acc);        // may share node w/ prev warp
                else *reinterpret_cast<float4*>(p) = acc;
                firstflush = false;
                acc = make_float4(0.f, 0.f, 0.f, 0.f);
                cur = dst0;
            }
            acc.x += m.x; acc.y += m.y; acc.z += m.z; acc.w += m.w;

            // shift pipeline
            x0 = x1; a0 = a1; dst0 = dst1;
            src1 = src2; dst1 = dst2; a1 = a2;
        }
        // final flush: may share node with next warp -> RED
        red_v4(&g_agg[(size_t)cur * DD + lane * 4], acc);
    }
}

// ---------------------------------------------------------------------------
// Node MLP: h=(1+eps)*x+agg; y=relu(h@W1+b1); x2=y@W2+b2
// 256 threads (8 warps), 6x8 per-thread tile, packed f32x2 FMAs.
// Fused epilogue: pool[batch[row]] += x2 (run-length RED.v4);
//                 x_cur = x2 + vn[l+1]; agg = 0 for next layer (except last).
// ---------------------------------------------------------------------------
__device__ __forceinline__ void tile_gemm6(
    const float* sA, const float* sW, int cg, int rg, u64 acc[6][4])
{
#pragma unroll 1
    for (int k = 0; k < DD; k += 4) {
        u64 w[4][4];
#pragma unroll
        for (int kk = 0; kk < 4; kk++) {
            const float4 wa = *reinterpret_cast<const float4*>(&sW[(k + kk) * DD + cg * 8]);
            const float4 wb = *reinterpret_cast<const float4*>(&sW[(k + kk) * DD + cg * 8 + 4]);
            w[kk][0] = pack2(wa.x, wa.y);
            w[kk][1] = pack2(wa.z, wa.w);
            w[kk][2] = pack2(wb.x, wb.y);
            w[kk][3] = pack2(wb.z, wb.w);
        }
        float4 a[6];
#pragma unroll
        for (int r = 0; r < 6; r++)
            a[r] = *reinterpret_cast<const float4*>(&sA[(rg * 6 + r) * DD + k]);
#pragma unroll
        for (int r = 0; r < 6; r++) {
            const u64 ax = pack2(a[r].x, a[r].x);
            fma2(acc[r][0], ax, w[0][0]); fma2(acc[r][1], ax, w[0][1]);
            fma2(acc[r][2], ax, w[0][2]); fma2(acc[r][3], ax, w[0][3]);
            const u64 ay = pack2(a[r].y, a[r].y);
            fma2(acc[r][0], ay, w[1][0]); fma2(acc[r][1], ay, w[1][1]);
            fma2(acc[r][2], ay, w[1][2]); fma2(acc[r][3], ay, w[1][3]);
            const u64 az = pack2(a[r].z, a[r].z);
            fma2(acc[r][0], az, w[2][0]); fma2(acc[r][1], az, w[2][1]);
            fma2(acc[r][2], az, w[2][2]); fma2(acc[r][3], az, w[2][3]);
            const u64 aw = pack2(a[r].w, a[r].w);
            fma2(acc[r][0], aw, w[3][0]); fma2(acc[r][1], aw, w[3][1]);
            fma2(acc[r][2], aw, w[3][2]); fma2(acc[r][3], aw, w[3][3]);
        }
    }
}

__global__ __launch_bounds__(NODE_T) void node_kernel(
    const float* __restrict__ w1, const float* __restrict__ b1,
    const float* __restrict__ w2, const float* __restrict__ b2,
    const float* __restrict__ epsp, const float* __restrict__ vn_next,
    const int* __restrict__ batch, int layer)
{
    extern __shared__ float sm[];
    float* sW1 = sm;                          // 64 KB
    float* sW2 = sm + DD * DD;                // 64 KB
    float* sH  = sm + 2 * DD * DD;            // 48 KB
    float* sY  = sH + TILE_R * DD;            // 48 KB
    int*   sB  = reinterpret_cast<int*>(sY + TILE_R * DD);  // 384 B
    const int t = threadIdx.x;

    for (int i = t; i < DD * DD / 4; i += NODE_T) {
        reinterpret_cast<float4*>(sW1)[i] = reinterpret_cast<const float4*>(w1)[i];
        reinterpret_cast<float4*>(sW2)[i] = reinterpret_cast<const float4*>(w2)[i];
    }
    const float epsv = 1.0f + *epsp;
    const int cg = t & 15;   // col group: 8 cols
    const int rg = t >> 4;   // row group: 6 rows (16 groups x 6 = 96)

    const float4 b1a = *reinterpret_cast<const float4*>(&b1[cg * 8]);
    const float4 b1b = *reinterpret_cast<const float4*>(&b1[cg * 8 + 4]);
    const float4 b2a = *reinterpret_cast<const float4*>(&b2[cg * 8]);
    const float4 b2b = *reinterpret_cast<const float4*>(&b2[cg * 8 + 4]);

    float4 vna = make_float4(0.f, 0.f, 0.f, 0.f), vnb = vna;
    if (vn_next) {
        vna = *reinterpret_cast<const float4*>(&vn_next[cg * 8]);
        vnb = *reinterpret_cast<const float4*>(&vn_next[cg * 8 + 4]);
    }
    const int zero_agg = (vn_next != nullptr);

    for (int tile = blockIdx.x; tile < NTILES; tile += gridDim.x) {
        const int row0 = tile * TILE_R;
        __syncthreads();   // protect sH/sY/sB reuse; also fences weight load (iter 0)

        // h tile = (1+eps)*x + agg ; stage batch ids
        for (int i = t; i < TILE_R; i += NODE_T)
            sB[i] = (row0 + i < NN) ? batch[row0 + i] : -1;
        for (int i = t; i < TILE_R * DD / 4; i += NODE_T) {
            const int row = row0 + (i >> 5);
            float4 hv = make_float4(0.f, 0.f, 0.f, 0.f);
            if (row < NN) {
                const int gi = row0 * (DD / 4) + i;
                const float4 xv = reinterpret_cast<const float4*>(g_xcur)[gi];
                const float4 av = reinterpret_cast<const float4*>(g_agg)[gi];
                hv.x = fmaf(epsv, xv.x, av.x);
                hv.y = fmaf(epsv, xv.y, av.y);
                hv.z = fmaf(epsv, xv.z, av.z);
                hv.w = fmaf(epsv, xv.w, av.w);
                if (zero_agg)
                    reinterpret_cast<float4*>(g_agg)[gi] = make_float4(0.f, 0.f, 0.f, 0.f);
            }
            reinterpret_cast<float4*>(sH)[i] = hv;
        }
        __syncthreads();

        u64 acc[6][4];
#pragma unroll
        for (int r = 0; r < 6; r++) {
            acc[r][0] = pack2(b1a.x, b1a.y); acc[r][1] = pack2(b1a.z, b1a.w);
            acc[r][2] = pack2(b1b.x, b1b.y); acc[r][3] = pack2(b1b.z, b1b.w);
        }
        tile_gemm6(sH, sW1, cg, rg, acc);
#pragma unroll
        for (int r = 0; r < 6; r++) {
            float* dst = &sY[(rg * 6 + r) * DD + cg * 8];
            const float2 p0 = unpack2(acc[r][0]), p1 = unpack2(acc[r][1]);
            const float2 p2 = unpack2(acc[r][2]), p3 = unpack2(acc[r][3]);
            *reinterpret_cast<float4*>(dst) =
                make_float4(fmaxf(p0.x, 0.f), fmaxf(p0.y, 0.f),
                            fmaxf(p1.x, 0.f), fmaxf(p1.y, 0.f));
            *reinterpret_cast<float4*>(dst + 4) =
                make_float4(fmaxf(p2.x, 0.f), fmaxf(p2.y, 0.f),
                            fmaxf(p3.x, 0.f), fmaxf(p3.y, 0.f));
        }
        __syncthreads();

#pragma unroll
        for (int r = 0; r < 6; r++) {
            acc[r][0] = pack2(b2a.x, b2a.y); acc[r][1] = pack2(b2a.z, b2a.w);
            acc[r][2] = pack2(b2b.x, b2b.y); acc[r][3] = pack2(b2b.z, b2b.w);
        }
        tile_gemm6(sY, sW2, cg, rg, acc);

        // Epilogue: pool RED (run-length reduced over sorted batch) + x_cur
        u64 ps0 = 0, ps1 = 0, ps2 = 0, ps3 = 0;
        int curb = -1;
#pragma unroll
        for (int r = 0; r < 6; r++) {
            const int lrow = rg * 6 + r;
            const int row = row0 + lrow;
            if (row >= NN) break;
            const int b = sB[lrow];
            if (b != curb) {
                if (curb >= 0) {
                    float* p = &g_pool[curb * JKD + layer * DD + cg * 8];
                    const float2 q0 = unpack2(ps0), q1 = unpack2(ps1);
                    const float2 q2 = unpack2(ps2), q3 = unpack2(ps3);
                    red_v4(p, make_float4(q0.x, q0.y, q1.x, q1.y));
                    red_v4(p + 4, make_float4(q2.x, q2.y, q3.x, q3.y));
                }
                curb = b; ps0 = ps1 = ps2 = ps3 = 0;
            }
            ps0 = add2(ps0, acc[r][0]); ps1 = add2(ps1, acc[r][1]);
            ps2 = add2(ps2, acc[r][2]); ps3 = add2(ps3, acc[r][3]);

            if (vn_next) {
                const float2 p0 = unpack2(acc[r][0]), p1 = unpack2(acc[r][1]);
                const float2 p2 = unpack2(acc[r][2]), p3 = unpack2(acc[r][3]);
                float* dst = &g_xcur[(size_t)row * DD + cg * 8];
                *reinterpret_cast<float4*>(dst) =
                    make_float4(p0.x + vna.x, p0.y + vna.y, p1.x + vna.z, p1.y + vna.w);
                *reinterpret_cast<float4*>(dst + 4) =
                    make_float4(p2.x + vnb.x, p2.y + vnb.y, p3.x + vnb.z, p3.y + vnb.w);
            }
        }
        if (curb >= 0) {
            float* p = &g_pool[curb * JKD + layer * DD + cg * 8];
            const float2 q0 = unpack2(ps0), q1 = unpack2(ps1);
            const float2 q2 = unpack2(ps2), q3 = unpack2(ps3);
            red_v4(p, make_float4(q0.x, q0.y, q1.x, q1.y));
            red_v4(p + 4, make_float4(q2.x, q2.y, q3.x, q3.y));
        }
    }
}

// ---------------------------------------------------------------------------
// Head: Linear(384->256) -> LN -> ReLU -> Linear(256->128) -> LN -> ReLU -> Linear(128->1)
// ---------------------------------------------------------------------------
__device__ __forceinline__ float2 block_sum2(float a, float b) {
    __shared__ float2 sred[8];
    const int lane = threadIdx.x & 31, w = threadIdx.x >> 5;
#pragma unroll
    for (int o = 16; o; o >>= 1) {
        a += __shfl_down_sync(0xffffffffu, a, o);
        b += __shfl_down_sync(0xffffffffu, b, o);
    }
    if (lane == 0) sred[w] = make_float2(a, b);
    __syncthreads();
    if (w == 0) {
        float2 s = (lane < 8) ? sred[lane] : make_float2(0.f, 0.f);
#pragma unroll
        for (int o = 4; o; o >>= 1) {
            s.x += __shfl_down_sync(0xffffffffu, s.x, o);
            s.y += __shfl_down_sync(0xffffffffu, s.y, o);
        }
        if (lane == 0) sred[0] = s;
    }
    __syncthreads();
    const float2 r = sred[0];
    __syncthreads();
    return r;
}

__global__ __launch_bounds__(256) void head_kernel(
    const float* __restrict__ w1, const float* __restrict__ b1,
    const float* __restrict__ ga1, const float* __restrict__ be1,
    const float* __restrict__ w2, const float* __restrict__ b2,
    const float* __restrict__ ga2, const float* __restrict__ be2,
    const float* __restrict__ ow, const float* __restrict__ ob,
    float* __restrict__ out)
{
    __shared__ float sg[JKD];
    __shared__ float s1[256];
    const int g = blockIdx.x, t = threadIdx.x;

    for (int i = t; i < JKD; i += 256) sg[i] = g_pool[g * JKD + i];
    __syncthreads();

    // stage 1: 384 -> 256
    float acc = b1[t];
#pragma unroll 4
    for (int k = 0; k < JKD; k++) acc = fmaf(sg[k], w1[k * 256 + t], acc);
    float2 s = block_sum2(acc, acc * acc);
    float mu = s.x * (1.f / 256.f);
    float var = s.y * (1.f / 256.f) - mu * mu;
    s1[t] = fmaxf((acc - mu) * rsqrtf(var + 1e-5f) * ga1[t] + be1[t], 0.f);
    __syncthreads();

    // stage 2: 256 -> 128
    float acc2 = 0.f;
    if (t < 128) {
        acc2 = b2[t];
#pragma unroll 4
        for (int k = 0; k < 256; k++) acc2 = fmaf(s1[k], w2[k * 128 + t], acc2);
    }
    const float cva = (t < 128) ? acc2 : 0.f;
    float2 s2 = block_sum2(cva, cva * cva);
    float mu2 = s2.x * (1.f / 128.f);
    float var2 = s2.y * (1.f / 128.f) - mu2 * mu2;
    float v2 = 0.f;
    if (t < 128) v2 = fmaxf((acc2 - mu2) * rsqrtf(var2 + 1e-5f) * ga2[t] + be2[t], 0.f);

    // stage 3: 128 -> 1
    const float p = (t < 128) ? v2 * ow[t] : 0.f;
    float2 s3 = block_sum2(p, 0.f);
    if (t == 0) out[g] = s3.x + ob[0];
}

// ---------------------------------------------------------------------------
extern "C" void kernel_launch(void* const* d_in, const int* in_sizes, int n_in,
                              void* d_out, int out_size) {
    (void)in_sizes; (void)n_in; (void)out_size;
    const float* x     = (const float*)d_in[0];
    const int*   ei    = (const int*)d_in[1];
    const float* ea    = (const float*)d_in[2];
    const int*   batch = (const int*)d_in[3];
    const float* vn    = (const float*)d_in[4];
    const float* ew    = (const float*)d_in[5];
    const float* ebias = (const float*)d_in[6];
    const float* eps   = (const float*)d_in[7];
    const float* mw1   = (const float*)d_in[8];
    const float* mb1   = (const float*)d_in[9];
    const float* mw2   = (const float*)d_in[10];
    const float* mb2   = (const float*)d_in[11];
    const float* lw1   = (const float*)d_in[12];
    const float* lb1   = (const float*)d_in[13];
    const float* ln1g  = (const float*)d_in[14];
    const float* ln1b  = (const float*)d_in[15];
    const float* lw2   = (const float*)d_in[16];
    const float* lb2   = (const float*)d_in[17];
    const float* ln2g  = (const float*)d_in[18];
    const float* ln2b  = (const float*)d_in[19];
    const float* ow    = (const float*)d_in[20];
    const float* ob    = (const float*)d_in[21];
    float* out = (float*)d_out;

    int nsm = 148;
    cudaDeviceGetAttribute(&nsm, cudaDevAttrMultiProcessorCount, 0);

    const int node_smem = (2 * DD * DD + 2 * TILE_R * DD) * (int)sizeof(float)
                        + TILE_R * (int)sizeof(int);                    // ~224.4 KB
    cudaFuncSetAttribute(node_kernel, cudaFuncAttributeMaxDynamicSharedMemorySize, node_smem);

    // init + CSR build (independent of layers)
    init_kernel<<<(NN * DD / 4 + 255) / 256, 256>>>(x, vn);
    k_zero_cnt<<<(ZERO_N + 255) / 256, 256>>>();
    k_hist<<<(EE + 255) / 256, 256>>>(ei);
    k_scan1<<<SCAN_NBLK, SCAN_BS>>>();
    k_scan2<<<1, SCAN_BS>>>();
    k_scan3<<<(NN + 255) / 256, 256>>>();
    k_scatter<<<(EE + 255) / 256, 256>>>(ei, ea);

    for (int i = 0; i < LLAYERS; i++) {
        agg_kernel<<<nsm * 2, 256>>>(ew + i * EDIM * DD, ebias + i * DD);
        node_kernel<<<nsm, NODE_T, node_smem>>>(
            mw1 + i * DD * DD, mb1 + i * DD,
            mw2 + i * DD * DD, mb2 + i * DD,
            eps + i,
            (i < LLAYERS - 1) ? (vn + (i + 1) * DD) : nullptr,
            batch, i);
    }

    head_kernel<<<GG, 256>>>(lw1, lb1, ln1g, ln1b, lw2, lb2, ln2g, ln2b, ow, ob, out);
}

// round 6
// speedup vs baseline: 1.2344x; 1.0232x over previous
#include <cuda_runtime.h>

#define NN 50000
#define DD 128
#define EE 600000
#define GG 512
#define LLAYERS 3
#define EDIM 16
#define JKD 384
#define TILE_R 96
#define NODE_T 256
#define NTILES ((NN + TILE_R - 1) / TILE_R)
#define CHUNK 32

typedef unsigned long long u64;

// Scratch (device globals: no runtime allocation allowed)
__device__ float g_xcur[NN * DD];          // 25.6 MB
__device__ float g_agg[NN * DD];           // 25.6 MB
__device__ float g_pool[GG * JKD];         // 0.79 MB
__device__ int   g_cnt[NN];
__device__ int   g_cursor[NN];
__device__ int   g_csr_src[EE];
__device__ int   g_csr_dst[EE];
__device__ float g_csr_ea[(size_t)EE * EDIM];   // 38.4 MB, edge attrs in CSR order

// ---------------------------------------------------------------------------
// packed f32x2 helpers (sm_103a)
// ---------------------------------------------------------------------------
__device__ __forceinline__ u64 pack2(float x, float y) {
    u64 r; asm("mov.b64 %0, {%1, %2};" : "=l"(r) : "f"(x), "f"(y)); return r;
}
__device__ __forceinline__ float2 unpack2(u64 v) {
    float2 r; asm("mov.b64 {%0, %1}, %2;" : "=f"(r.x), "=f"(r.y) : "l"(v)); return r;
}
__device__ __forceinline__ void fma2(u64& d, u64 a, u64 b) {
    asm("fma.rn.f32x2 %0, %1, %2, %0;" : "+l"(d) : "l"(a), "l"(b));
}
__device__ __forceinline__ u64 add2(u64 a, u64 b) {
    u64 r; asm("add.rn.f32x2 %0, %1, %2;" : "=l"(r) : "l"(a), "l"(b)); return r;
}
__device__ __forceinline__ void red_v4(float* p, float4 v) {
    asm volatile("red.global.add.v4.f32 [%0], {%1,%2,%3,%4};"
                 :: "l"(p), "f"(v.x), "f"(v.y), "f"(v.z), "f"(v.w) : "memory");
}

// ---------------------------------------------------------------------------
// init: x_cur = x + vn_emb[0]; agg = 0; g_cnt = 0; g_pool = 0
// ---------------------------------------------------------------------------
__global__ void init_kernel(const float* __restrict__ x, const float* __restrict__ vn0) {
    int i = blockIdx.x * blockDim.x + threadIdx.x;   // float4 index
    if (i < NN) g_cnt[i] = 0;
    if (i < GG * JKD / 4)
        reinterpret_cast<float4*>(g_pool)[i] = make_float4(0.f, 0.f, 0.f, 0.f);
    if (i >= NN * DD / 4) return;
    float4 xv = reinterpret_cast<const float4*>(x)[i];
    float4 vv = reinterpret_cast<const float4*>(vn0)[i & 31];
    xv.x += vv.x; xv.y += vv.y; xv.z += vv.z; xv.w += vv.w;
    reinterpret_cast<float4*>(g_xcur)[i] = xv;
    reinterpret_cast<float4*>(g_agg)[i] = make_float4(0.f, 0.f, 0.f, 0.f);
}

// ---------------------------------------------------------------------------
// CSR build: histogram -> single-block scan -> scatter (src, dst, attr copy)
// ---------------------------------------------------------------------------
__global__ void k_hist(const int* __restrict__ ei) {
    int e = blockIdx.x * blockDim.x + threadIdx.x;
    if (e < EE) atomicAdd(&g_cnt[ei[EE + e]], 1);
}

__global__ __launch_bounds__(1024) void k_scan_single() {
    __shared__ int s[1024];
    const int t = threadIdx.x;
    const int per = (NN + 1023) / 1024;   // 49
    const int base = t * per;
    int lim = NN - base;
    if (lim < 0) lim = 0;
    if (lim > per) lim = per;
    int loc = 0;
    for (int i = 0; i < lim; i++) loc += g_cnt[base + i];
    s[t] = loc;
    __syncthreads();
#pragma unroll
    for (int o = 1; o < 1024; o <<= 1) {
        int u = (t >= o) ? s[t - o] : 0;
        __syncthreads();
        s[t] += u;
        __syncthreads();
    }
    int run = (t > 0) ? s[t - 1] : 0;   // exclusive prefix
    for (int i = 0; i < lim; i++) {
        const int c = g_cnt[base + i];
        g_cursor[base + i] = run;
        run += c;
    }
}

__global__ void k_scatter(const int* __restrict__ ei, const float* __restrict__ ea) {
    int e = blockIdx.x * blockDim.x + threadIdx.x;
    if (e >= EE) return;
    const int dst = ei[EE + e];
    const int pos = atomicAdd(&g_cursor[dst], 1);
    g_csr_src[pos] = ei[e];
    g_csr_dst[pos] = dst;
    const float4* q = reinterpret_cast<const float4*>(&ea[(size_t)e * EDIM]);
    float4* s = reinterpret_cast<float4*>(&g_csr_ea[(size_t)pos * EDIM]);
    s[0] = q[0]; s[1] = q[1]; s[2] = q[2]; s[3] = q[3];
}

// ---------------------------------------------------------------------------
// Aggregation: flat edge partition over dst-sorted CSR stream.
// Encoder uses pairwise-k packed FMAs with attr pairs read via LDS.64
// BROADCAST from a double-buffered per-warp smem stage — NO shuffles.
// Flush on dst change: interior nodes plain STG, range-boundary nodes RED.v4.
// ---------------------------------------------------------------------------
__global__ __launch_bounds__(256, 2) void agg_kernel(
    const float* __restrict__ ew, const float* __restrict__ ebias)
{
    __shared__ float s_attr[8][2][CHUNK * EDIM];   // 8 warps x dbl x 2KB = 32KB
    __shared__ int2  s_sd[8][2][CHUNK];            // 4KB

    const int lane = threadIdx.x & 31;
    const int w = threadIdx.x >> 5;

    // per-lane weights: wp[j][c] = (W[2j][col], W[2j+1][col]), col = lane*4+c
    u64 wp[8][4];
#pragma unroll
    for (int j = 0; j < 8; j++)
#pragma unroll
        for (int c = 0; c < 4; c++)
            wp[j][c] = pack2(ew[(2 * j) * DD + lane * 4 + c],
                             ew[(2 * j + 1) * DD + lane * 4 + c]);
    const float4 bq = *reinterpret_cast<const float4*>(&ebias[lane * 4]);

    const int warp = (blockIdx.x * blockDim.x + threadIdx.x) >> 5;
    const int nw = (gridDim.x * blockDim.x) >> 5;
    const int epw = (EE + nw - 1) / nw;
    const int beg = warp * epw;
    if (beg >= EE) return;
    const int range = ((beg + epw < EE) ? beg + epw : EE) - beg;
    const int nchunks = (range + CHUNK - 1) / CHUNK;

    // stage chunk 0
    {
        const int cnt = (range < CHUNK) ? range : CHUNK;
        const float4* src4 = reinterpret_cast<const float4*>(&g_csr_ea[(size_t)beg * EDIM]);
        float4* dst4 = reinterpret_cast<float4*>(&s_attr[w][0][0]);
        for (int i = lane; i < cnt * 4; i += 32) dst4[i] = src4[i];
        if (lane < cnt) s_sd[w][0][lane] = make_int2(g_csr_src[beg + lane], g_csr_dst[beg + lane]);
    }
    __syncwarp();

    // prime pipeline
    int2 sd0 = s_sd[w][0][0];
    float4 x0 = *reinterpret_cast<const float4*>(&g_xcur[(size_t)sd0.x * DD + lane * 4]);

    float4 acc = make_float4(0.f, 0.f, 0.f, 0.f);
    int cur = sd0.y;
    bool firstflush = true;
    int gpos = 0;
    int buf = 0;

    for (int c = 0; c < nchunks; c++) {
        const int cbeg = c * CHUNK;
        const int cnt = ((range - cbeg) < CHUNK) ? (range - cbeg) : CHUNK;

        __syncwarp();   // all lanes done reading buf^1 (used by chunk c-1)
        if (c + 1 < nchunks) {
            const int nbeg = beg + cbeg + CHUNK;
            const int ncnt = ((range - cbeg - CHUNK) < CHUNK) ? (range - cbeg - CHUNK) : CHUNK;
            const float4* src4 = reinterpret_cast<const float4*>(&g_csr_ea[(size_t)nbeg * EDIM]);
            float4* dst4 = reinterpret_cast<float4*>(&s_attr[w][buf ^ 1][0]);
            for (int i = lane; i < ncnt * 4; i += 32) dst4[i] = src4[i];
            if (lane < ncnt)
                s_sd[w][buf ^ 1][lane] = make_int2(g_csr_src[nbeg + lane], g_csr_dst[nbeg + lane]);
        }
        __syncwarp();

        for (int i = 0; i < cnt; i++) {
            // peek next edge + prefetch its x row
            const bool more = (gpos + 1 < range);
            int2 sd1 = sd0;
            float4 x1 = make_float4(0.f, 0.f, 0.f, 0.f);
            if (more) {
                sd1 = (i + 1 < cnt) ? s_sd[w][buf][i + 1] : s_sd[w][buf ^ 1][0];
                x1 = *reinterpret_cast<const float4*>(&g_xcur[(size_t)sd1.x * DD + lane * 4]);
            }

            // encoder: pairwise-k, attr pairs via LDS broadcast
            const u64* ap = reinterpret_cast<const u64*>(&s_attr[w][buf][i * EDIM]);
            u64 ac0 = pack2(bq.x, 0.f), ac1 = pack2(bq.y, 0.f);
            u64 ac2 = pack2(bq.z, 0.f), ac3 = pack2(bq.w, 0.f);
#pragma unroll
            for (int j = 0; j < 8; j++) {
                const u64 aj = ap[j];
                fma2(ac0, aj, wp[j][0]);
                fma2(ac1, aj, wp[j][1]);
                fma2(ac2, aj, wp[j][2]);
                fma2(ac3, aj, wp[j][3]);
            }
            const float2 q0 = unpack2(ac0), q1 = unpack2(ac1);
            const float2 q2 = unpack2(ac2), q3 = unpack2(ac3);
            const float m0 = fmaxf(q0.x + q0.y + x0.x, 0.f);
            const float m1 = fmaxf(q1.x + q1.y + x0.y, 0.f);
            const float m2 = fmaxf(q2.x + q2.y + x0.z, 0.f);
            const float m3 = fmaxf(q3.x + q3.y + x0.w, 0.f);

            if (sd0.y != cur) {   // warp-uniform
                float* p = &g_agg[(size_t)cur * DD + lane * 4];
                if (firstflush) red_v4(p, acc);         // may share node w/ prev warp
                else *reinterpret_cast<float4*>(p) = acc;
                firstflush = false;
                acc = make_float4(0.f, 0.f, 0.f, 0.f);
                cur = sd0.y;
            }
            acc.x += m0; acc.y += m1; acc.z += m2; acc.w += m3;

            x0 = x1; sd0 = sd1; gpos++;
        }
        buf ^= 1;
    }
    // final flush: may share node with next warp
    red_v4(&g_agg[(size_t)cur * DD + lane * 4], acc);
}

// ---------------------------------------------------------------------------
// Node MLP: h=(1+eps)*x+agg; y=relu(h@W1+b1); x2=y@W2+b2
// 256 threads, 6x8 per-thread tile, packed f32x2 FMAs.
// Fused epilogue: pool[batch[row]] += x2 (run-length RED.v4);
//                 x_cur = x2 + vn[l+1]; agg = 0 for next layer (except last).
// ---------------------------------------------------------------------------
__device__ __forceinline__ void tile_gemm6(
    const float* sA, const float* sW, int cg, int rg, u64 acc[6][4])
{
#pragma unroll 1
    for (int k = 0; k < DD; k += 4) {
        u64 w[4][4];
#pragma unroll
        for (int kk = 0; kk < 4; kk++) {
            const float4 wa = *reinterpret_cast<const float4*>(&sW[(k + kk) * DD + cg * 8]);
            const float4 wb = *reinterpret_cast<const float4*>(&sW[(k + kk) * DD + cg * 8 + 4]);
            w[kk][0] = pack2(wa.x, wa.y);
            w[kk][1] = pack2(wa.z, wa.w);
            w[kk][2] = pack2(wb.x, wb.y);
            w[kk][3] = pack2(wb.z, wb.w);
        }
        float4 a[6];
#pragma unroll
        for (int r = 0; r < 6; r++)
            a[r] = *reinterpret_cast<const float4*>(&sA[(rg * 6 + r) * DD + k]);
#pragma unroll
        for (int r = 0; r < 6; r++) {
            const u64 ax = pack2(a[r].x, a[r].x);
            fma2(acc[r][0], ax, w[0][0]); fma2(acc[r][1], ax, w[0][1]);
            fma2(acc[r][2], ax, w[0][2]); fma2(acc[r][3], ax, w[0][3]);
            const u64 ay = pack2(a[r].y, a[r].y);
            fma2(acc[r][0], ay, w[1][0]); fma2(acc[r][1], ay, w[1][1]);
            fma2(acc[r][2], ay, w[1][2]); fma2(acc[r][3], ay, w[1][3]);
            const u64 az = pack2(a[r].z, a[r].z);
            fma2(acc[r][0], az, w[2][0]); fma2(acc[r][1], az, w[2][1]);
            fma2(acc[r][2], az, w[2][2]); fma2(acc[r][3], az, w[2][3]);
            const u64 aw = pack2(a[r].w, a[r].w);
            fma2(acc[r][0], aw, w[3][0]); fma2(acc[r][1], aw, w[3][1]);
            fma2(acc[r][2], aw, w[3][2]); fma2(acc[r][3], aw, w[3][3]);
        }
    }
}

__global__ __launch_bounds__(NODE_T) void node_kernel(
    const float* __restrict__ w1, const float* __restrict__ b1,
    const float* __restrict__ w2, const float* __restrict__ b2,
    const float* __restrict__ epsp, const float* __restrict__ vn_next,
    const int* __restrict__ batch, int layer)
{
    extern __shared__ float sm[];
    float* sW1 = sm;                          // 64 KB
    float* sW2 = sm + DD * DD;                // 64 KB
    float* sH  = sm + 2 * DD * DD;            // 48 KB
    float* sY  = sH + TILE_R * DD;            // 48 KB
    int*   sB  = reinterpret_cast<int*>(sY + TILE_R * DD);  // 384 B
    const int t = threadIdx.x;

    for (int i = t; i < DD * DD / 4; i += NODE_T) {
        reinterpret_cast<float4*>(sW1)[i] = reinterpret_cast<const float4*>(w1)[i];
        reinterpret_cast<float4*>(sW2)[i] = reinterpret_cast<const float4*>(w2)[i];
    }
    const float epsv = 1.0f + *epsp;
    const int cg = t & 15;   // col group: 8 cols
    const int rg = t >> 4;   // row group: 6 rows (16 groups x 6 = 96)

    const float4 b1a = *reinterpret_cast<const float4*>(&b1[cg * 8]);
    const float4 b1b = *reinterpret_cast<const float4*>(&b1[cg * 8 + 4]);
    const float4 b2a = *reinterpret_cast<const float4*>(&b2[cg * 8]);
    const float4 b2b = *reinterpret_cast<const float4*>(&b2[cg * 8 + 4]);

    float4 vna = make_float4(0.f, 0.f, 0.f, 0.f), vnb = vna;
    if (vn_next) {
        vna = *reinterpret_cast<const float4*>(&vn_next[cg * 8]);
        vnb = *reinterpret_cast<const float4*>(&vn_next[cg * 8 + 4]);
    }
    const int zero_agg = (vn_next != nullptr);

    for (int tile = blockIdx.x; tile < NTILES; tile += gridDim.x) {
        const int row0 = tile * TILE_R;
        __syncthreads();   // protect sH/sY/sB reuse; also fences weight load (iter 0)

        // h tile = (1+eps)*x + agg ; stage batch ids; zero agg for next layer
        for (int i = t; i < TILE_R; i += NODE_T)
            sB[i] = (row0 + i < NN) ? batch[row0 + i] : -1;
        for (int i = t; i < TILE_R * DD / 4; i += NODE_T) {
            const int row = row0 + (i >> 5);
            float4 hv = make_float4(0.f, 0.f, 0.f, 0.f);
            if (row < NN) {
                const int gi = row0 * (DD / 4) + i;
                const float4 xv = reinterpret_cast<const float4*>(g_xcur)[gi];
                const float4 av = reinterpret_cast<const float4*>(g_agg)[gi];
                hv.x = fmaf(epsv, xv.x, av.x);
                hv.y = fmaf(epsv, xv.y, av.y);
                hv.z = fmaf(epsv, xv.z, av.z);
                hv.w = fmaf(epsv, xv.w, av.w);
                if (zero_agg)
                    reinterpret_cast<float4*>(g_agg)[gi] = make_float4(0.f, 0.f, 0.f, 0.f);
            }
            reinterpret_cast<float4*>(sH)[i] = hv;
        }
        __syncthreads();

        u64 acc[6][4];
#pragma unroll
        for (int r = 0; r < 6; r++) {
            acc[r][0] = pack2(b1a.x, b1a.y); acc[r][1] = pack2(b1a.z, b1a.w);
            acc[r][2] = pack2(b1b.x, b1b.y); acc[r][3] = pack2(b1b.z, b1b.w);
        }
        tile_gemm6(sH, sW1, cg, rg, acc);
#pragma unroll
        for (int r = 0; r < 6; r++) {
            float* dst = &sY[(rg * 6 + r) * DD + cg * 8];
            const float2 p0 = unpack2(acc[r][0]), p1 = unpack2(acc[r][1]);
            const float2 p2 = unpack2(acc[r][2]), p3 = unpack2(acc[r][3]);
            *reinterpret_cast<float4*>(dst) =
                make_float4(fmaxf(p0.x, 0.f), fmaxf(p0.y, 0.f),
                            fmaxf(p1.x, 0.f), fmaxf(p1.y, 0.f));
            *reinterpret_cast<float4*>(dst + 4) =
                make_float4(fmaxf(p2.x, 0.f), fmaxf(p2.y, 0.f),
                            fmaxf(p3.x, 0.f), fmaxf(p3.y, 0.f));
        }
        __syncthreads();

#pragma unroll
        for (int r = 0; r < 6; r++) {
            acc[r][0] = pack2(b2a.x, b2a.y); acc[r][1] = pack2(b2a.z, b2a.w);
            acc[r][2] = pack2(b2b.x, b2b.y); acc[r][3] = pack2(b2b.z, b2b.w);
        }
        tile_gemm6(sY, sW2, cg, rg, acc);

        // Epilogue: pool RED (run-length reduced over sorted batch) + x_cur
        u64 ps0 = 0, ps1 = 0, ps2 = 0, ps3 = 0;
        int curb = -1;
#pragma unroll
        for (int r = 0; r < 6; r++) {
            const int lrow = rg * 6 + r;
            const int row = row0 + lrow;
            if (row >= NN) break;
            const int b = sB[lrow];
            if (b != curb) {
                if (curb >= 0) {
                    float* p = &g_pool[curb * JKD + layer * DD + cg * 8];
                    const float2 q0 = unpack2(ps0), q1 = unpack2(ps1);
                    const float2 q2 = unpack2(ps2), q3 = unpack2(ps3);
                    red_v4(p, make_float4(q0.x, q0.y, q1.x, q1.y));
                    red_v4(p + 4, make_float4(q2.x, q2.y, q3.x, q3.y));
                }
                curb = b; ps0 = ps1 = ps2 = ps3 = 0;
            }
            ps0 = add2(ps0, acc[r][0]); ps1 = add2(ps1, acc[r][1]);
            ps2 = add2(ps2, acc[r][2]); ps3 = add2(ps3, acc[r][3]);

            if (vn_next) {
                const float2 p0 = unpack2(acc[r][0]), p1 = unpack2(acc[r][1]);
                const float2 p2 = unpack2(acc[r][2]), p3 = unpack2(acc[r][3]);
                float* dst = &g_xcur[(size_t)row * DD + cg * 8];
                *reinterpret_cast<float4*>(dst) =
                    make_float4(p0.x + vna.x, p0.y + vna.y, p1.x + vna.z, p1.y + vna.w);
                *reinterpret_cast<float4*>(dst + 4) =
                    make_float4(p2.x + vnb.x, p2.y + vnb.y, p3.x + vnb.z, p3.y + vnb.w);
            }
        }
        if (curb >= 0) {
            float* p = &g_pool[curb * JKD + layer * DD + cg * 8];
            const float2 q0 = unpack2(ps0), q1 = unpack2(ps1);
            const float2 q2 = unpack2(ps2), q3 = unpack2(ps3);
            red_v4(p, make_float4(q0.x, q0.y, q1.x, q1.y));
            red_v4(p + 4, make_float4(q2.x, q2.y, q3.x, q3.y));
        }
    }
}

// ---------------------------------------------------------------------------
// Head: Linear(384->256) -> LN -> ReLU -> Linear(256->128) -> LN -> ReLU -> Linear(128->1)
// ---------------------------------------------------------------------------
__device__ __forceinline__ float2 block_sum2(float a, float b) {
    __shared__ float2 sred[8];
    const int lane = threadIdx.x & 31, w = threadIdx.x >> 5;
#pragma unroll
    for (int o = 16; o; o >>= 1) {
        a += __shfl_down_sync(0xffffffffu, a, o);
        b += __shfl_down_sync(0xffffffffu, b, o);
    }
    if (lane == 0) sred[w] = make_float2(a, b);
    __syncthreads();
    if (w == 0) {
        float2 s = (lane < 8) ? sred[lane] : make_float2(0.f, 0.f);
#pragma unroll
        for (int o = 4; o; o >>= 1) {
            s.x += __shfl_down_sync(0xffffffffu, s.x, o);
            s.y += __shfl_down_sync(0xffffffffu, s.y, o);
        }
        if (lane == 0) sred[0] = s;
    }
    __syncthreads();
    const float2 r = sred[0];
    __syncthreads();
    return r;
}

__global__ __launch_bounds__(256) void head_kernel(
    const float* __restrict__ w1, const float* __restrict__ b1,
    const float* __restrict__ ga1, const float* __restrict__ be1,
    const float* __restrict__ w2, const float* __restrict__ b2,
    const float* __restrict__ ga2, const float* __restrict__ be2,
    const float* __restrict__ ow, const float* __restrict__ ob,
    float* __restrict__ out)
{
    __shared__ float sg[JKD];
    __shared__ float s1[256];
    const int g = blockIdx.x, t = threadIdx.x;

    for (int i = t; i < JKD; i += 256) sg[i] = g_pool[g * JKD + i];
    __syncthreads();

    // stage 1: 384 -> 256
    float acc = b1[t];
#pragma unroll 4
    for (int k = 0; k < JKD; k++) acc = fmaf(sg[k], w1[k * 256 + t], acc);
    float2 s = block_sum2(acc, acc * acc);
    float mu = s.x * (1.f / 256.f);
    float var = s.y * (1.f / 256.f) - mu * mu;
    s1[t] = fmaxf((acc - mu) * rsqrtf(var + 1e-5f) * ga1[t] + be1[t], 0.f);
    __syncthreads();

    // stage 2: 256 -> 128
    float acc2 = 0.f;
    if (t < 128) {
        acc2 = b2[t];
#pragma unroll 4
        for (int k = 0; k < 256; k++) acc2 = fmaf(s1[k], w2[k * 128 + t], acc2);
    }
    const float cva = (t < 128) ? acc2 : 0.f;
    float2 s2 = block_sum2(cva, cva * cva);
    float mu2 = s2.x * (1.f / 128.f);
    float var2 = s2.y * (1.f / 128.f) - mu2 * mu2;
    float v2 = 0.f;
    if (t < 128) v2 = fmaxf((acc2 - mu2) * rsqrtf(var2 + 1e-5f) * ga2[t] + be2[t], 0.f);

    // stage 3: 128 -> 1
    const float p = (t < 128) ? v2 * ow[t] : 0.f;
    float2 s3 = block_sum2(p, 0.f);
    if (t == 0) out[g] = s3.x + ob[0];
}

// ---------------------------------------------------------------------------
extern "C" void kernel_launch(void* const* d_in, const int* in_sizes, int n_in,
                              void* d_out, int out_size) {
    (void)in_sizes; (void)n_in; (void)out_size;
    const float* x     = (const float*)d_in[0];
    const int*   ei    = (const int*)d_in[1];
    const float* ea    = (const float*)d_in[2];
    const int*   batch = (const int*)d_in[3];
    const float* vn    = (const float*)d_in[4];
    const float* ew    = (const float*)d_in[5];
    const float* ebias = (const float*)d_in[6];
    const float* eps   = (const float*)d_in[7];
    const float* mw1   = (const float*)d_in[8];
    const float* mb1   = (const float*)d_in[9];
    const float* mw2   = (const float*)d_in[10];
    const float* mb2   = (const float*)d_in[11];
    const float* lw1   = (const float*)d_in[12];
    const float* lb1   = (const float*)d_in[13];
    const float* ln1g  = (const float*)d_in[14];
    const float* ln1b  = (const float*)d_in[15];
    const float* lw2   = (const float*)d_in[16];
    const float* lb2   = (const float*)d_in[17];
    const float* ln2g  = (const float*)d_in[18];
    const float* ln2b  = (const float*)d_in[19];
    const float* ow    = (const float*)d_in[20];
    const float* ob    = (const float*)d_in[21];
    float* out = (float*)d_out;

    int nsm = 148;
    cudaDeviceGetAttribute(&nsm, cudaDevAttrMultiProcessorCount, 0);

    const int node_smem = (2 * DD * DD + 2 * TILE_R * DD) * (int)sizeof(float)
                        + TILE_R * (int)sizeof(int);                    // ~224.4 KB
    cudaFuncSetAttribute(node_kernel, cudaFuncAttributeMaxDynamicSharedMemorySize, node_smem);

    // init + CSR build
    init_kernel<<<(NN * DD / 4 + 255) / 256, 256>>>(x, vn);
    k_hist<<<(EE + 255) / 256, 256>>>(ei);
    k_scan_single<<<1, 1024>>>();
    k_scatter<<<(EE + 255) / 256, 256>>>(ei, ea);

    for (int i = 0; i < LLAYERS; i++) {
        agg_kernel<<<nsm * 2, 256>>>(ew + i * EDIM * DD, ebias + i * DD);
        node_kernel<<<nsm, NODE_T, node_smem>>>(
            mw1 + i * DD * DD, mb1 + i * DD,
            mw2 + i * DD * DD, mb2 + i * DD,
            eps + i,
            (i < LLAYERS - 1) ? (vn + (i + 1) * DD) : nullptr,
            batch, i);
    }

    head_kernel<<<GG, 256>>>(lw1, lb1, ln1g, ln1b, lw2, lb2, ln2g, ln2b, ow, ob, out);
}